// round 4
// baseline (speedup 1.0000x reference)
#include <cuda_runtime.h>
#include <cuda_fp16.h>
#include <cstdint>

// ---------------------------------------------------------------------------
// LSTM cell, fused, sm_103 plain target (no tcgen05 — ptxas compiles via
// compute_103). Legacy HMMA pipe is rate-bound (~494 MAC/cyc/SM), so:
//  - A is loaded as raw fp32 (no separate convert kernel); HMMA A-fragments
//    built in-register via cvt.rn.f16x2.f32.
//  - Last 64 K-columns are computed on the (otherwise idle) FMA pipe in fp32,
//    interleaved with the tensor mainloop, into the same accumulators.
// CTA 128x256, 8 warps of 64x64, 3-stage cp.async pipeline.
// ---------------------------------------------------------------------------

#define BDIM 65536
#define HDIM 512
#define DIN  256
#define NTOT 2048
#define KTOT 768

#define BM 128
#define BN 256
#define BK 32
#define STAGES 3
#define KTEN 704                  // tensor-core K columns
#define NCH (KTEN / BK)           // 22 chunks
#define KFF 64                    // FFMA-pipe K columns (h_old cols 448..511)

#define ROWA 144                  // A row: 32 f32 = 128B + 16 pad
#define ROWB 80                   // B row: 32 fp16 = 64B + 16 pad
#define A_ST (BM * ROWA)          // 18432
#define B_ST (BN * ROWB)          // 20480
#define STAGE_BYTES (A_ST + B_ST) // 38912

#define SM_BIAS  0                                  // 1024 B
#define SM_STAGE 1024
#define SM_A2    (SM_STAGE + STAGES * STAGE_BYTES)  // 117760, 2*18432
#define SM_B2    (SM_A2 + 2 * A_ST)                 // 154624, 64*1024
#define SM_TOTAL (SM_B2 + KFF * 1024)               // 220160

// epilogue overlay (stage area is free by then)
#define ROWE 68
#define HB_OFF SM_STAGE
#define CB_OFF (SM_STAGE + BM * ROWE * 4)

__device__ __half g_Bp[(size_t)NTOT * KTOT];     // fp16 weights (tensor part)
__device__ float  g_Bff[(size_t)KFF * NTOT];     // fp32 weights (FFMA part)
__device__ float  g_bias[NTOT];

// ---------------------------------------------------------------------------
__device__ __forceinline__ uint32_t smem_u32(const void* p) {
    uint32_t a;
    asm("{ .reg .u64 t; cvta.to.shared.u64 t, %1; cvt.u32.u64 %0, t; }"
        : "=r"(a) : "l"(p));
    return a;
}
__device__ __forceinline__ void cp16(uint32_t sa, const void* g) {
    asm volatile("cp.async.cg.shared.global [%0], [%1], 16;" :: "r"(sa), "l"(g));
}
#define LDSM4(r0, r1, r2, r3, a)                                              \
    asm volatile("ldmatrix.sync.aligned.m8n8.x4.shared.b16 {%0,%1,%2,%3}, [%4];" \
        : "=r"(r0), "=r"(r1), "=r"(r2), "=r"(r3) : "r"(a))
__device__ __forceinline__ uint32_t pack_h2(float hi, float lo) {
    uint32_t d;
    asm("cvt.rn.f16x2.f32 %0, %1, %2;" : "=r"(d) : "f"(hi), "f"(lo));
    return d;
}
__device__ __forceinline__ void mma16816(float* c, const uint32_t* a, const uint32_t* b) {
    asm volatile(
        "mma.sync.aligned.m16n8k16.row.col.f32.f16.f16.f32 "
        "{%0,%1,%2,%3}, {%4,%5,%6,%7}, {%8,%9}, {%0,%1,%2,%3};"
        : "+f"(c[0]), "+f"(c[1]), "+f"(c[2]), "+f"(c[3])
        : "r"(a[0]), "r"(a[1]), "r"(a[2]), "r"(a[3]), "r"(b[0]), "r"(b[1]));
}
__device__ __forceinline__ float tanh_fast(float x) {
    float y;
    asm("tanh.approx.f32 %0, %1;" : "=f"(y) : "f"(x));
    return y;
}
__device__ __forceinline__ float sigmoid_fast(float x) {
    return fmaf(0.5f, tanh_fast(0.5f * x), 0.5f);
}

// ---------------------------------------------------------------------------
// Pack: fp16 weights (k<704) interleaved n=4h+g, fp32 weights (k>=704), bias
// ---------------------------------------------------------------------------
__global__ void pack_weights(const float* __restrict__ U, const float* __restrict__ W,
                             const float* __restrict__ bU, const float* __restrict__ bW) {
    int idx = blockIdx.x * blockDim.x + threadIdx.x;
    const int total = KTOT * HDIM;
    if (idx < total) {
        int k = idx / HDIM;
        int h = idx - k * HDIM;
        #pragma unroll
        for (int g = 0; g < 4; g++) {
            float v = (k < DIN) ? U[((size_t)g * DIN + k) * HDIM + h]
                                : W[((size_t)g * HDIM + (k - DIN)) * HDIM + h];
            int n = h * 4 + g;
            if (k < KTEN) g_Bp[(size_t)n * KTOT + k] = __float2half_rn(v);
            else          g_Bff[(size_t)(k - KTEN) * NTOT + n] = v;
        }
    }
    if (idx < NTOT) {
        int h = idx >> 2, g = idx & 3;
        g_bias[idx] = bU[g * HDIM + h] + bW[g * HDIM + h];
    }
}

// ---------------------------------------------------------------------------
__device__ __forceinline__ void load_chunk(int kc, int s, uint32_t sb,
                                           const float* __restrict__ X,
                                           const float* __restrict__ Hold,
                                           int mtile, int n0) {
    const int tid = threadIdx.x;
    const uint32_t a_base = sb + SM_STAGE + s * STAGE_BYTES;
    const uint32_t b_base = a_base + A_ST;

    const float* asrc;
    int ld, colb;
    if (kc < 8) { asrc = X;    ld = DIN;  colb = kc * BK; }
    else        { asrc = Hold; ld = HDIM; colb = (kc - 8) * BK; }

    // A fp32: 128 rows x 8 x 16B
    #pragma unroll
    for (int i = 0; i < 4; i++) {
        int op = tid + i * 256;
        int r = op >> 3, seg = op & 7;
        const float* g = asrc + (size_t)(mtile * BM + r) * ld + colb + seg * 4;
        cp16(a_base + r * ROWA + seg * 16, g);
    }
    // B fp16: 256 rows x 4 x 16B
    #pragma unroll
    for (int i = 0; i < 4; i++) {
        int op = tid + i * 256;
        int r = op >> 2, seg = op & 3;
        const __half* g = g_Bp + (size_t)(n0 + r) * KTOT + kc * BK + seg * 8;
        cp16(b_base + r * ROWB + seg * 16, g);
    }
}

__global__ void __launch_bounds__(256, 1)
lstm_gemm(const float* __restrict__ X, const float* __restrict__ Hold,
          const float* __restrict__ Cold, float* __restrict__ out) {
    extern __shared__ char smem[];
    const uint32_t sb = smem_u32(smem);
    const int tid = threadIdx.x;
    const int wid = tid >> 5, lane = tid & 31;
    const int g8 = lane >> 2, tg = lane & 3;
    const int ntile = blockIdx.x & 7;          // 8 consecutive CTAs share A
    const int mtile = blockIdx.x >> 3;
    const int n0 = ntile * BN;

    const int wm = wid & 1;                    // M half (0..1), rows wm*64
    const int wn = wid >> 1;                   // N quarter (0..3), cols wn*64

    ((float*)(smem + SM_BIAS))[tid] = g_bias[n0 + tid];

    float acc[4][8][4];
    #pragma unroll
    for (int mt = 0; mt < 4; mt++)
        #pragma unroll
        for (int j = 0; j < 8; j++)
            #pragma unroll
            for (int q = 0; q < 4; q++) acc[mt][j][q] = 0.f;

    // ---- prologue: group 0 = FFMA-region (A2 + B2), then stage 0, stage 1 ----
    // A2: h_old cols 448..511, 2 chunks of 32
    #pragma unroll
    for (int i = 0; i < 8; i++) {
        int op = tid + i * 256;
        int cc = op >> 10, rem = op & 1023;
        int r = rem >> 3, seg = rem & 7;
        const float* g = Hold + (size_t)(mtile * BM + r) * HDIM + 448 + cc * 32 + seg * 4;
        cp16(sb + SM_A2 + cc * A_ST + r * ROWA + seg * 16, g);
    }
    // B2: fp32 [64 k][256 n-slice]
    #pragma unroll
    for (int i = 0; i < 16; i++) {
        int op = tid + i * 256;
        int kk = op >> 6, seg = op & 63;
        const float* g = g_Bff + (size_t)kk * NTOT + n0 + seg * 4;
        cp16(sb + SM_B2 + kk * 1024 + seg * 16, g);
    }
    asm volatile("cp.async.commit_group;");

    #pragma unroll
    for (int kc = 0; kc < STAGES - 1; kc++) {
        load_chunk(kc, kc, sb, X, Hold, mtile, n0);
        asm volatile("cp.async.commit_group;");
    }

    const float* sA2 = (const float*)(smem + SM_A2);
    const float* sB2 = (const float*)(smem + SM_B2);

    #pragma unroll 1
    for (int kc = 0; kc < NCH; kc++) {
        asm volatile("cp.async.wait_group 1;");
        __syncthreads();

        if (kc + STAGES - 1 < NCH)
            load_chunk(kc + STAGES - 1, (kc + STAGES - 1) % STAGES, sb, X, Hold, mtile, n0);
        asm volatile("cp.async.commit_group;");

        const int s = kc % STAGES;
        const uint32_t a_base = sb + SM_STAGE + s * STAGE_BYTES;
        const uint32_t b_base = a_base + A_ST;

        // ---- tensor part: 2 x k16 steps ----
        #pragma unroll
        for (int ks = 0; ks < 2; ks++) {
            uint32_t af[4][4];
            #pragma unroll
            for (int mt = 0; mt < 4; mt++) {
                uint32_t r0 = (wm * 64 + mt * 16 + g8) * ROWA + (ks * 16 + tg * 2) * 4;
                float2 v0 = *(const float2*)(smem + a_base - sb + r0);
                float2 v1 = *(const float2*)(smem + a_base - sb + r0 + 8 * ROWA);
                float2 v2 = *(const float2*)(smem + a_base - sb + r0 + 32);
                float2 v3 = *(const float2*)(smem + a_base - sb + r0 + 8 * ROWA + 32);
                af[mt][0] = pack_h2(v0.y, v0.x);
                af[mt][1] = pack_h2(v1.y, v1.x);
                af[mt][2] = pack_h2(v2.y, v2.x);
                af[mt][3] = pack_h2(v3.y, v3.x);
            }
            uint32_t bf[8][2];
            #pragma unroll
            for (int jp = 0; jp < 4; jp++) {
                uint32_t row = wn * 64 + jp * 16 + (lane & 7) + ((lane >> 4) & 1) * 8;
                uint32_t addr = b_base + row * ROWB + ks * 32 + ((lane >> 3) & 1) * 16;
                LDSM4(bf[2 * jp][0], bf[2 * jp][1], bf[2 * jp + 1][0], bf[2 * jp + 1][1], addr);
            }
            #pragma unroll
            for (int mt = 0; mt < 4; mt++)
                #pragma unroll
                for (int j = 0; j < 8; j++)
                    mma16816(acc[mt][j], af[mt], bf[j]);
        }

        // ---- FFMA part: 3 columns of the KFF region per iteration ----
        const int f0 = kc * 3;
        #pragma unroll
        for (int t = 0; t < 3; t++) {
            int fk = f0 + t;
            if (fk < KFF) {
                float a8[8];
                #pragma unroll
                for (int mt = 0; mt < 4; mt++) {
                    int base = (fk >> 5) * (A_ST / 4) + ((wm * 64 + mt * 16 + g8) * ROWA + (fk & 31) * 4) / 4;
                    a8[2 * mt]     = sA2[base];
                    a8[2 * mt + 1] = sA2[base + 2 * ROWA];  // +8 rows (ROWA/4 floats each)
                }
                #pragma unroll
                for (int j = 0; j < 8; j++) {
                    float2 b2 = *(const float2*)(sB2 + fk * 256 + wn * 64 + j * 8 + tg * 2);
                    #pragma unroll
                    for (int mt = 0; mt < 4; mt++) {
                        acc[mt][j][0] = fmaf(a8[2 * mt],     b2.x, acc[mt][j][0]);
                        acc[mt][j][1] = fmaf(a8[2 * mt],     b2.y, acc[mt][j][1]);
                        acc[mt][j][2] = fmaf(a8[2 * mt + 1], b2.x, acc[mt][j][2]);
                        acc[mt][j][3] = fmaf(a8[2 * mt + 1], b2.y, acc[mt][j][3]);
                    }
                }
            }
        }
    }

    // ---------------- epilogue ----------------
    __syncthreads();                                  // stage smem now free

    const float* cg = Cold + (size_t)(mtile * BM) * HDIM + ntile * 64;
    #pragma unroll
    for (int i = 0; i < 8; i++) {
        int idx = tid + i * 256;
        int row = idx >> 4, c4 = idx & 15;
        float4 v = *(const float4*)(cg + (size_t)row * HDIM + c4 * 4);
        *(float4*)(smem + CB_OFF + (row * ROWE + c4 * 4) * 4) = v;
    }
    __syncthreads();

    float* cb = (float*)(smem + CB_OFF);
    float* hb = (float*)(smem + HB_OFF);
    const float4* sbias4 = (const float4*)(smem + SM_BIAS);
    const int odd = tg & 1;

    #pragma unroll
    for (int mt = 0; mt < 4; mt++) {
        #pragma unroll
        for (int j = 0; j < 8; j++) {
            float c0 = acc[mt][j][0], c1 = acc[mt][j][1];
            float c2 = acc[mt][j][2], c3 = acc[mt][j][3];
            float e0 = __shfl_xor_sync(0xffffffffu, c0, 1);
            float e1 = __shfl_xor_sync(0xffffffffu, c1, 1);
            float e2 = __shfl_xor_sync(0xffffffffu, c2, 1);
            float e3 = __shfl_xor_sync(0xffffffffu, c3, 1);
            float gi = odd ? e2 : c0;
            float gf = odd ? e3 : c1;
            float go = odd ? c2 : e0;
            float gc = odd ? c3 : e1;
            int row = wm * 64 + mt * 16 + g8 + (odd ? 8 : 0);
            int hl = wn * 16 + 2 * j + (tg >> 1);
            float4 bb = sbias4[hl];
            float cold = cb[row * ROWE + hl];
            float it = sigmoid_fast(gi + bb.x);
            float ft = sigmoid_fast(gf + bb.y);
            float ot = sigmoid_fast(go + bb.z);
            float ct = tanh_fast(gc + bb.w);
            float cn = fmaf(it, ct, ft * cold);
            float hn = ot * tanh_fast(cn);
            cb[row * ROWE + hl] = cn;
            hb[row * ROWE + hl] = hn;
        }
    }
    __syncthreads();

    float* oh = out + (size_t)(mtile * BM) * HDIM + ntile * 64;
    float* oc = oh + (size_t)BDIM * HDIM;
    #pragma unroll
    for (int i = 0; i < 8; i++) {
        int idx = tid + i * 256;
        int row = idx >> 4, c4 = idx & 15;
        *(float4*)(oh + (size_t)row * HDIM + c4 * 4) =
            *(const float4*)(smem + HB_OFF + (row * ROWE + c4 * 4) * 4);
        *(float4*)(oc + (size_t)row * HDIM + c4 * 4) =
            *(const float4*)(smem + CB_OFF + (row * ROWE + c4 * 4) * 4);
    }
}

// ---------------------------------------------------------------------------
extern "C" void kernel_launch(void* const* d_in, const int* in_sizes, int n_in,
                              void* d_out, int out_size) {
    const float* X    = (const float*)d_in[0];
    const float* Hold = (const float*)d_in[1];
    const float* Cold = (const float*)d_in[2];
    const float* U    = (const float*)d_in[3];
    const float* bU   = (const float*)d_in[4];
    const float* W    = (const float*)d_in[5];
    const float* bW   = (const float*)d_in[6];
    float* out = (float*)d_out;
    (void)in_sizes; (void)n_in; (void)out_size;

    cudaFuncSetAttribute(lstm_gemm, cudaFuncAttributeMaxDynamicSharedMemorySize, SM_TOTAL);

    pack_weights<<<(KTOT * HDIM + 255) / 256, 256>>>(U, W, bU, bW);

    const int grid = (BDIM / BM) * (NTOT / BN);   // 512 * 8 = 4096
    lstm_gemm<<<grid, 256, SM_TOTAL>>>(X, Hold, Cold, out);
}

// round 5
// speedup vs baseline: 1.7631x; 1.7631x over previous
#include <cuda_runtime.h>
#include <cuda_fp16.h>
#include <cstdint>

// ---------------------------------------------------------------------------
// LSTM cell, fused, sm_103 plain target (no tcgen05).
// R5: issue-bound fix — 2 CTAs/SM x 256 thr (4 warps/SMSP), CTA tile 128x128,
// warp tile 32x64, 3-stage cp.async, ldmatrix fragments, fused LSTM epilogue.
//   A[b,k]  = fp16([X | h_old])   [65536, 768]   (convert_act)
//   Bp[n,k] = fp16 packed, n=4h+g (gates interleaved along N)
//   G = A @ Bp^T  fp32 accum  ->  gates -> h_new, c_new
// ---------------------------------------------------------------------------

#define BDIM 65536
#define HDIM 512
#define DIN  256
#define NTOT 2048
#define KTOT 768

#define BM 128
#define BN 128
#define BK 32
#define STAGES 3
#define NCH (KTOT / BK)            // 24

#define ROWB 80                    // 32 fp16 = 64B + 16B pad (ldmatrix safe)
#define A_BYTES (BM * ROWB)        // 10240
#define B_BYTES (BN * ROWB)        // 10240
#define STAGE_BYTES (A_BYTES + B_BYTES)           // 20480
#define SM_BIAS 0                                  // 512 B used
#define SM_AB   1024
#define SM_TOTAL (SM_AB + STAGES * STAGE_BYTES)    // 62464

// epilogue overlay (stage area free by then): 128 rows x 32 h-cols, pad to 36
#define ROWE 36
#define HB_OFF SM_AB
#define CB_OFF (SM_AB + BM * ROWE * 4)             // 1024 + 18432

__device__ __half g_Apack[(size_t)BDIM * KTOT];    // 96 MB
__device__ __half g_Bp[(size_t)NTOT * KTOT];       // 3 MB
__device__ float  g_bias[NTOT];

// ---------------------------------------------------------------------------
__device__ __forceinline__ uint32_t smem_u32(const void* p) {
    uint32_t a;
    asm("{ .reg .u64 t; cvta.to.shared.u64 t, %1; cvt.u32.u64 %0, t; }"
        : "=r"(a) : "l"(p));
    return a;
}
__device__ __forceinline__ void cp16(uint32_t sa, const void* g) {
    asm volatile("cp.async.cg.shared.global [%0], [%1], 16;" :: "r"(sa), "l"(g));
}
#define LDSM4(r0, r1, r2, r3, a)                                              \
    asm volatile("ldmatrix.sync.aligned.m8n8.x4.shared.b16 {%0,%1,%2,%3}, [%4];" \
        : "=r"(r0), "=r"(r1), "=r"(r2), "=r"(r3) : "r"(a))

__device__ __forceinline__ void mma16816(float* c, const uint32_t* a, const uint32_t* b) {
    asm volatile(
        "mma.sync.aligned.m16n8k16.row.col.f32.f16.f16.f32 "
        "{%0,%1,%2,%3}, {%4,%5,%6,%7}, {%8,%9}, {%0,%1,%2,%3};"
        : "+f"(c[0]), "+f"(c[1]), "+f"(c[2]), "+f"(c[3])
        : "r"(a[0]), "r"(a[1]), "r"(a[2]), "r"(a[3]), "r"(b[0]), "r"(b[1]));
}
__device__ __forceinline__ float tanh_fast(float x) {
    float y;
    asm("tanh.approx.f32 %0, %1;" : "=f"(y) : "f"(x));
    return y;
}
__device__ __forceinline__ float sigmoid_fast(float x) {
    return fmaf(0.5f, tanh_fast(0.5f * x), 0.5f);
}

// ---------------------------------------------------------------------------
// Prep kernels
// ---------------------------------------------------------------------------
__global__ void convert_act(const float* __restrict__ X, const float* __restrict__ H) {
    size_t idx = (size_t)blockIdx.x * blockDim.x + threadIdx.x;
    size_t e = idx * 4;
    if (e >= (size_t)BDIM * KTOT) return;
    size_t b = e / KTOT;
    int k = (int)(e - b * KTOT);
    float4 v;
    if (k < DIN) v = *(const float4*)(X + b * DIN + k);
    else         v = *(const float4*)(H + b * HDIM + (k - DIN));
    __half2 lo = __floats2half2_rn(v.x, v.y);
    __half2 hi = __floats2half2_rn(v.z, v.w);
    *(uint2*)(g_Apack + e) = make_uint2(*(uint32_t*)&lo, *(uint32_t*)&hi);
}

__global__ void pack_weights(const float* __restrict__ U, const float* __restrict__ W,
                             const float* __restrict__ bU, const float* __restrict__ bW) {
    int idx = blockIdx.x * blockDim.x + threadIdx.x;
    const int total = KTOT * HDIM;
    if (idx < total) {
        int k = idx / HDIM;
        int h = idx - k * HDIM;
        #pragma unroll
        for (int g = 0; g < 4; g++) {
            float v = (k < DIN) ? U[((size_t)g * DIN + k) * HDIM + h]
                                : W[((size_t)g * HDIM + (k - DIN)) * HDIM + h];
            g_Bp[(size_t)(h * 4 + g) * KTOT + k] = __float2half_rn(v);
        }
    }
    if (idx < NTOT) {
        int h = idx >> 2, g = idx & 3;
        g_bias[idx] = bU[g * HDIM + h] + bW[g * HDIM + h];
    }
}

// ---------------------------------------------------------------------------
// Main fused GEMM
// ---------------------------------------------------------------------------
__device__ __forceinline__ void load_chunk(int kc, int s, uint32_t sb,
                                           int mtile, int n0) {
    const int tid = threadIdx.x;
    const uint32_t a_base = sb + SM_AB + s * STAGE_BYTES;
    const uint32_t b_base = a_base + A_BYTES;
    // A: 128 rows x 4 x 16B = 512 ops
    #pragma unroll
    for (int i = 0; i < 2; i++) {
        int op = tid + i * 256;
        int r = op >> 2, seg = op & 3;
        const __half* g = g_Apack + (size_t)(mtile * BM + r) * KTOT + kc * BK + seg * 8;
        cp16(a_base + r * ROWB + seg * 16, g);
    }
    // B: 128 rows x 4 x 16B = 512 ops
    #pragma unroll
    for (int i = 0; i < 2; i++) {
        int op = tid + i * 256;
        int r = op >> 2, seg = op & 3;
        const __half* g = g_Bp + (size_t)(n0 + r) * KTOT + kc * BK + seg * 8;
        cp16(b_base + r * ROWB + seg * 16, g);
    }
}

__global__ void __launch_bounds__(256, 2)
lstm_gemm(const float* __restrict__ Cold, float* __restrict__ out) {
    extern __shared__ char smem[];
    const uint32_t sb = smem_u32(smem);
    const int tid = threadIdx.x;
    const int wid = tid >> 5, lane = tid & 31;
    const int g8 = lane >> 2, tg = lane & 3;
    const int ntile = blockIdx.x & 15;          // 16 consecutive CTAs share A
    const int mtile = blockIdx.x >> 4;
    const int n0 = ntile * BN;

    // warp grid 4(M) x 2(N); warp tile 32 x 64
    const int wm = wid & 3;                     // rows wm*32
    const int wn = wid >> 2;                    // cols wn*64

    if (tid < 128) ((float*)(smem + SM_BIAS))[tid] = g_bias[n0 + tid];

    float acc[2][8][4];
    #pragma unroll
    for (int mt = 0; mt < 2; mt++)
        #pragma unroll
        for (int j = 0; j < 8; j++)
            #pragma unroll
            for (int q = 0; q < 4; q++) acc[mt][j][q] = 0.f;

    #pragma unroll
    for (int kc = 0; kc < STAGES - 1; kc++) {
        load_chunk(kc, kc, sb, mtile, n0);
        asm volatile("cp.async.commit_group;");
    }

    #pragma unroll 1
    for (int kc = 0; kc < NCH; kc++) {
        asm volatile("cp.async.wait_group 1;");
        __syncthreads();

        if (kc + STAGES - 1 < NCH)
            load_chunk(kc + STAGES - 1, (kc + STAGES - 1) % STAGES, sb, mtile, n0);
        asm volatile("cp.async.commit_group;");

        const int s = kc % STAGES;
        const uint32_t a_base = sb + SM_AB + s * STAGE_BYTES;
        const uint32_t b_base = a_base + A_BYTES;

        #pragma unroll
        for (int ks = 0; ks < 2; ks++) {
            const uint32_t kb = ks * 32;
            uint32_t af[2][4];
            #pragma unroll
            for (int mt = 0; mt < 2; mt++) {
                uint32_t row = wm * 32 + mt * 16 + (lane & 7) + ((lane >> 3) & 1) * 8;
                uint32_t addr = a_base + row * ROWB + kb + ((lane >> 4) & 1) * 16;
                LDSM4(af[mt][0], af[mt][1], af[mt][2], af[mt][3], addr);
            }
            uint32_t bf[8][2];
            #pragma unroll
            for (int jp = 0; jp < 4; jp++) {
                uint32_t row = wn * 64 + jp * 16 + (lane & 7) + ((lane >> 4) & 1) * 8;
                uint32_t addr = b_base + row * ROWB + kb + ((lane >> 3) & 1) * 16;
                LDSM4(bf[2 * jp][0], bf[2 * jp][1], bf[2 * jp + 1][0], bf[2 * jp + 1][1], addr);
            }
            #pragma unroll
            for (int mt = 0; mt < 2; mt++)
                #pragma unroll
                for (int j = 0; j < 8; j++)
                    mma16816(acc[mt][j], af[mt], bf[j]);
        }
    }

    // ---------------- epilogue ----------------
    __syncthreads();                            // stage smem now free

    // stage Cold coalesced: 128 rows x 32 h-cols (this ntile covers 32 h)
    const float* cg = Cold + (size_t)(mtile * BM) * HDIM + ntile * 32;
    #pragma unroll
    for (int i = 0; i < 4; i++) {
        int idx = tid + i * 256;
        int row = idx >> 3, c4 = idx & 7;
        float4 v = *(const float4*)(cg + (size_t)row * HDIM + c4 * 4);
        *(float4*)(smem + CB_OFF + (row * ROWE + c4 * 4) * 4) = v;
    }
    __syncthreads();

    float* cb = (float*)(smem + CB_OFF);
    float* hb = (float*)(smem + HB_OFF);
    const float4* sbias4 = (const float4*)(smem + SM_BIAS);
    const int odd = tg & 1;

    #pragma unroll
    for (int mt = 0; mt < 2; mt++) {
        #pragma unroll
        for (int j = 0; j < 8; j++) {
            float c0 = acc[mt][j][0], c1 = acc[mt][j][1];
            float c2 = acc[mt][j][2], c3 = acc[mt][j][3];
            float e0 = __shfl_xor_sync(0xffffffffu, c0, 1);
            float e1 = __shfl_xor_sync(0xffffffffu, c1, 1);
            float e2 = __shfl_xor_sync(0xffffffffu, c2, 1);
            float e3 = __shfl_xor_sync(0xffffffffu, c3, 1);
            // even lane: row g8, gates (c0,c1,e0,e1); odd: row g8+8, (e2,e3,c2,c3)
            float gi = odd ? e2 : c0;
            float gf = odd ? e3 : c1;
            float go = odd ? c2 : e0;
            float gc = odd ? c3 : e1;
            int row = wm * 32 + mt * 16 + g8 + (odd ? 8 : 0);
            int hl = wn * 16 + 2 * j + (tg >> 1);
            float4 bb = sbias4[hl];
            float cold = cb[row * ROWE + hl];
            float it = sigmoid_fast(gi + bb.x);
            float ft = sigmoid_fast(gf + bb.y);
            float ot = sigmoid_fast(go + bb.z);
            float ct = tanh_fast(gc + bb.w);
            float cn = fmaf(it, ct, ft * cold);
            float hn = ot * tanh_fast(cn);
            cb[row * ROWE + hl] = cn;
            hb[row * ROWE + hl] = hn;
        }
    }
    __syncthreads();

    // coalesced writeback
    float* oh = out + (size_t)(mtile * BM) * HDIM + ntile * 32;
    float* oc = oh + (size_t)BDIM * HDIM;
    #pragma unroll
    for (int i = 0; i < 4; i++) {
        int idx = tid + i * 256;
        int row = idx >> 3, c4 = idx & 7;
        *(float4*)(oh + (size_t)row * HDIM + c4 * 4) =
            *(const float4*)(smem + HB_OFF + (row * ROWE + c4 * 4) * 4);
        *(float4*)(oc + (size_t)row * HDIM + c4 * 4) =
            *(const float4*)(smem + CB_OFF + (row * ROWE + c4 * 4) * 4);
    }
}

// ---------------------------------------------------------------------------
extern "C" void kernel_launch(void* const* d_in, const int* in_sizes, int n_in,
                              void* d_out, int out_size) {
    const float* X    = (const float*)d_in[0];
    const float* Hold = (const float*)d_in[1];
    const float* Cold = (const float*)d_in[2];
    const float* U    = (const float*)d_in[3];
    const float* bU   = (const float*)d_in[4];
    const float* W    = (const float*)d_in[5];
    const float* bW   = (const float*)d_in[6];
    float* out = (float*)d_out;
    (void)in_sizes; (void)n_in; (void)out_size;

    cudaFuncSetAttribute(lstm_gemm, cudaFuncAttributeMaxDynamicSharedMemorySize, SM_TOTAL);

    const size_t act_elems = (size_t)BDIM * KTOT;
    convert_act<<<(unsigned)((act_elems / 4 + 255) / 256), 256>>>(X, Hold);
    pack_weights<<<(KTOT * HDIM + 255) / 256, 256>>>(U, W, bU, bW);

    const int grid = (BDIM / BM) * (NTOT / BN);   // 512 * 16 = 8192
    lstm_gemm<<<grid, 256, SM_TOTAL>>>(Cold, out);
}

// round 6
// speedup vs baseline: 1.8366x; 1.0417x over previous
#include <cuda_runtime.h>
#include <cuda_fp16.h>
#include <cstdint>

// ---------------------------------------------------------------------------
// LSTM cell, fused, sm_103 plain target (no tcgen05).
// R6: R5 config (2 CTAs/SM x 256 thr, CTA 128x128, warp 32x64, ldmatrix,
// fused epilogue) + 4-stage pipeline w/ wait_group 2 + single prep kernel
// (2 launches per replay: prep, gemm).
//   A[b,k]  = fp16([X | h_old])   [65536, 768]
//   Bp[n,k] = fp16 packed, n=4h+g (gates interleaved along N)
//   G = A @ Bp^T  fp32 accum  ->  gates -> h_new, c_new
// ---------------------------------------------------------------------------

#define BDIM 65536
#define HDIM 512
#define DIN  256
#define NTOT 2048
#define KTOT 768

#define BM 128
#define BN 128
#define BK 32
#define STAGES 4
#define NCH (KTOT / BK)            // 24

#define ROWB 80                    // 32 fp16 = 64B + 16B pad (ldmatrix safe)
#define A_BYTES (BM * ROWB)        // 10240
#define B_BYTES (BN * ROWB)        // 10240
#define STAGE_BYTES (A_BYTES + B_BYTES)           // 20480
#define SM_BIAS 0                                  // 512 B used
#define SM_AB   1024
#define SM_TOTAL (SM_AB + STAGES * STAGE_BYTES)    // 82944  (x2 CTAs = 166KB)

// epilogue overlay (stage area free by then): 128 rows x 32 h-cols, pad to 36
#define ROWE 36
#define HB_OFF SM_AB
#define CB_OFF (SM_AB + BM * ROWE * 4)             // 1024 + 18432

#define CONV_BLOCKS 49152          // convert part of prep grid
#define PACK_BLOCKS 1536           // pack part of prep grid

__device__ __half g_Apack[(size_t)BDIM * KTOT];    // 96 MB
__device__ __half g_Bp[(size_t)NTOT * KTOT];       // 3 MB
__device__ float  g_bias[NTOT];

// ---------------------------------------------------------------------------
__device__ __forceinline__ uint32_t smem_u32(const void* p) {
    uint32_t a;
    asm("{ .reg .u64 t; cvta.to.shared.u64 t, %1; cvt.u32.u64 %0, t; }"
        : "=r"(a) : "l"(p));
    return a;
}
__device__ __forceinline__ void cp16(uint32_t sa, const void* g) {
    asm volatile("cp.async.cg.shared.global [%0], [%1], 16;" :: "r"(sa), "l"(g));
}
#define LDSM4(r0, r1, r2, r3, a)                                              \
    asm volatile("ldmatrix.sync.aligned.m8n8.x4.shared.b16 {%0,%1,%2,%3}, [%4];" \
        : "=r"(r0), "=r"(r1), "=r"(r2), "=r"(r3) : "r"(a))

__device__ __forceinline__ void mma16816(float* c, const uint32_t* a, const uint32_t* b) {
    asm volatile(
        "mma.sync.aligned.m16n8k16.row.col.f32.f16.f16.f32 "
        "{%0,%1,%2,%3}, {%4,%5,%6,%7}, {%8,%9}, {%0,%1,%2,%3};"
        : "+f"(c[0]), "+f"(c[1]), "+f"(c[2]), "+f"(c[3])
        : "r"(a[0]), "r"(a[1]), "r"(a[2]), "r"(a[3]), "r"(b[0]), "r"(b[1]));
}
__device__ __forceinline__ float tanh_fast(float x) {
    float y;
    asm("tanh.approx.f32 %0, %1;" : "=f"(y) : "f"(x));
    return y;
}
__device__ __forceinline__ float sigmoid_fast(float x) {
    return fmaf(0.5f, tanh_fast(0.5f * x), 0.5f);
}

// ---------------------------------------------------------------------------
// Prep: activations -> fp16 (blocks [0, CONV_BLOCKS)),
//       weights -> fp16 interleaved + bias (blocks [CONV_BLOCKS, ...))
// ---------------------------------------------------------------------------
__global__ void prep(const float* __restrict__ X, const float* __restrict__ H,
                     const float* __restrict__ U, const float* __restrict__ W,
                     const float* __restrict__ bU, const float* __restrict__ bW) {
    if (blockIdx.x < CONV_BLOCKS) {
        size_t idx = (size_t)blockIdx.x * blockDim.x + threadIdx.x;
        size_t e = idx * 4;
        size_t b = e / KTOT;
        int k = (int)(e - b * KTOT);
        float4 v;
        if (k < DIN) v = *(const float4*)(X + b * DIN + k);
        else         v = *(const float4*)(H + b * HDIM + (k - DIN));
        __half2 lo = __floats2half2_rn(v.x, v.y);
        __half2 hi = __floats2half2_rn(v.z, v.w);
        *(uint2*)(g_Apack + e) = make_uint2(*(uint32_t*)&lo, *(uint32_t*)&hi);
    } else {
        int idx = (blockIdx.x - CONV_BLOCKS) * blockDim.x + threadIdx.x;
        const int total = KTOT * HDIM;
        if (idx < total) {
            int k = idx / HDIM;
            int h = idx - k * HDIM;
            #pragma unroll
            for (int g = 0; g < 4; g++) {
                float v = (k < DIN) ? U[((size_t)g * DIN + k) * HDIM + h]
                                    : W[((size_t)g * HDIM + (k - DIN)) * HDIM + h];
                g_Bp[(size_t)(h * 4 + g) * KTOT + k] = __float2half_rn(v);
            }
        }
        if (idx < NTOT) {
            int h = idx >> 2, g = idx & 3;
            g_bias[idx] = bU[g * HDIM + h] + bW[g * HDIM + h];
        }
    }
}

// ---------------------------------------------------------------------------
// Main fused GEMM
// ---------------------------------------------------------------------------
__device__ __forceinline__ void load_chunk(int kc, int s, uint32_t sb,
                                           int mtile, int n0) {
    const int tid = threadIdx.x;
    const uint32_t a_base = sb + SM_AB + s * STAGE_BYTES;
    const uint32_t b_base = a_base + A_BYTES;
    // A: 128 rows x 4 x 16B = 512 ops
    #pragma unroll
    for (int i = 0; i < 2; i++) {
        int op = tid + i * 256;
        int r = op >> 2, seg = op & 3;
        const __half* g = g_Apack + (size_t)(mtile * BM + r) * KTOT + kc * BK + seg * 8;
        cp16(a_base + r * ROWB + seg * 16, g);
    }
    // B: 128 rows x 4 x 16B = 512 ops
    #pragma unroll
    for (int i = 0; i < 2; i++) {
        int op = tid + i * 256;
        int r = op >> 2, seg = op & 3;
        const __half* g = g_Bp + (size_t)(n0 + r) * KTOT + kc * BK + seg * 8;
        cp16(b_base + r * ROWB + seg * 16, g);
    }
}

__global__ void __launch_bounds__(256, 2)
lstm_gemm(const float* __restrict__ Cold, float* __restrict__ out) {
    extern __shared__ char smem[];
    const uint32_t sb = smem_u32(smem);
    const int tid = threadIdx.x;
    const int wid = tid >> 5, lane = tid & 31;
    const int g8 = lane >> 2, tg = lane & 3;
    const int ntile = blockIdx.x & 15;          // 16 consecutive CTAs share A
    const int mtile = blockIdx.x >> 4;
    const int n0 = ntile * BN;

    // warp grid 4(M) x 2(N); warp tile 32 x 64
    const int wm = wid & 3;                     // rows wm*32
    const int wn = wid >> 2;                    // cols wn*64

    if (tid < 128) ((float*)(smem + SM_BIAS))[tid] = g_bias[n0 + tid];

    float acc[2][8][4];
    #pragma unroll
    for (int mt = 0; mt < 2; mt++)
        #pragma unroll
        for (int j = 0; j < 8; j++)
            #pragma unroll
            for (int q = 0; q < 4; q++) acc[mt][j][q] = 0.f;

    #pragma unroll
    for (int kc = 0; kc < STAGES - 1; kc++) {
        load_chunk(kc, kc, sb, mtile, n0);
        asm volatile("cp.async.commit_group;");
    }

    #pragma unroll 1
    for (int kc = 0; kc < NCH; kc++) {
        asm volatile("cp.async.wait_group 2;");
        __syncthreads();

        if (kc + STAGES - 1 < NCH)
            load_chunk(kc + STAGES - 1, (kc + STAGES - 1) & 3, sb, mtile, n0);
        asm volatile("cp.async.commit_group;");

        const int s = kc & 3;
        const uint32_t a_base = sb + SM_AB + s * STAGE_BYTES;
        const uint32_t b_base = a_base + A_BYTES;

        #pragma unroll
        for (int ks = 0; ks < 2; ks++) {
            const uint32_t kb = ks * 32;
            uint32_t af[2][4];
            #pragma unroll
            for (int mt = 0; mt < 2; mt++) {
                uint32_t row = wm * 32 + mt * 16 + (lane & 7) + ((lane >> 3) & 1) * 8;
                uint32_t addr = a_base + row * ROWB + kb + ((lane >> 4) & 1) * 16;
                LDSM4(af[mt][0], af[mt][1], af[mt][2], af[mt][3], addr);
            }
            uint32_t bf[8][2];
            #pragma unroll
            for (int jp = 0; jp < 4; jp++) {
                uint32_t row = wn * 64 + jp * 16 + (lane & 7) + ((lane >> 4) & 1) * 8;
                uint32_t addr = b_base + row * ROWB + kb + ((lane >> 3) & 1) * 16;
                LDSM4(bf[2 * jp][0], bf[2 * jp][1], bf[2 * jp + 1][0], bf[2 * jp + 1][1], addr);
            }
            #pragma unroll
            for (int mt = 0; mt < 2; mt++)
                #pragma unroll
                for (int j = 0; j < 8; j++)
                    mma16816(acc[mt][j], af[mt], bf[j]);
        }
    }

    // ---------------- epilogue ----------------
    __syncthreads();                            // stage smem now free

    // stage Cold coalesced: 128 rows x 32 h-cols (this ntile covers 32 h)
    const float* cg = Cold + (size_t)(mtile * BM) * HDIM + ntile * 32;
    #pragma unroll
    for (int i = 0; i < 4; i++) {
        int idx = tid + i * 256;
        int row = idx >> 3, c4 = idx & 7;
        float4 v = *(const float4*)(cg + (size_t)row * HDIM + c4 * 4);
        *(float4*)(smem + CB_OFF + (row * ROWE + c4 * 4) * 4) = v;
    }
    __syncthreads();

    float* cb = (float*)(smem + CB_OFF);
    float* hb = (float*)(smem + HB_OFF);
    const float4* sbias4 = (const float4*)(smem + SM_BIAS);
    const int odd = tg & 1;

    #pragma unroll
    for (int mt = 0; mt < 2; mt++) {
        #pragma unroll
        for (int j = 0; j < 8; j++) {
            float c0 = acc[mt][j][0], c1 = acc[mt][j][1];
            float c2 = acc[mt][j][2], c3 = acc[mt][j][3];
            float e0 = __shfl_xor_sync(0xffffffffu, c0, 1);
            float e1 = __shfl_xor_sync(0xffffffffu, c1, 1);
            float e2 = __shfl_xor_sync(0xffffffffu, c2, 1);
            float e3 = __shfl_xor_sync(0xffffffffu, c3, 1);
            // even lane: row g8, gates (c0,c1,e0,e1); odd: row g8+8, (e2,e3,c2,c3)
            float gi = odd ? e2 : c0;
            float gf = odd ? e3 : c1;
            float go = odd ? c2 : e0;
            float gc = odd ? c3 : e1;
            int row = wm * 32 + mt * 16 + g8 + (odd ? 8 : 0);
            int hl = wn * 16 + 2 * j + (tg >> 1);
            float4 bb = sbias4[hl];
            float cold = cb[row * ROWE + hl];
            float it = sigmoid_fast(gi + bb.x);
            float ft = sigmoid_fast(gf + bb.y);
            float ot = sigmoid_fast(go + bb.z);
            float ct = tanh_fast(gc + bb.w);
            float cn = fmaf(it, ct, ft * cold);
            float hn = ot * tanh_fast(cn);
            cb[row * ROWE + hl] = cn;
            hb[row * ROWE + hl] = hn;
        }
    }
    __syncthreads();

    // coalesced writeback
    float* oh = out + (size_t)(mtile * BM) * HDIM + ntile * 32;
    float* oc = oh + (size_t)BDIM * HDIM;
    #pragma unroll
    for (int i = 0; i < 4; i++) {
        int idx = tid + i * 256;
        int row = idx >> 3, c4 = idx & 7;
        *(float4*)(oh + (size_t)row * HDIM + c4 * 4) =
            *(const float4*)(smem + HB_OFF + (row * ROWE + c4 * 4) * 4);
        *(float4*)(oc + (size_t)row * HDIM + c4 * 4) =
            *(const float4*)(smem + CB_OFF + (row * ROWE + c4 * 4) * 4);
    }
}

// ---------------------------------------------------------------------------
extern "C" void kernel_launch(void* const* d_in, const int* in_sizes, int n_in,
                              void* d_out, int out_size) {
    const float* X    = (const float*)d_in[0];
    const float* Hold = (const float*)d_in[1];
    const float* Cold = (const float*)d_in[2];
    const float* U    = (const float*)d_in[3];
    const float* bU   = (const float*)d_in[4];
    const float* W    = (const float*)d_in[5];
    const float* bW   = (const float*)d_in[6];
    float* out = (float*)d_out;
    (void)in_sizes; (void)n_in; (void)out_size;

    cudaFuncSetAttribute(lstm_gemm, cudaFuncAttributeMaxDynamicSharedMemorySize, SM_TOTAL);

    prep<<<CONV_BLOCKS + PACK_BLOCKS, 256>>>(X, Hold, U, W, bU, bW);

    const int grid = (BDIM / BM) * (NTOT / BN);   // 512 * 16 = 8192
    lstm_gemm<<<grid, 256, SM_TOTAL>>>(Cold, out);
}